// round 17
// baseline (speedup 1.0000x reference)
#include <cuda_runtime.h>

typedef unsigned long long u64;

// ---- packed f32x2 helpers (sm_100+ PTX) ----
__device__ __forceinline__ u64 pk2(float a, float b) {
    u64 r; asm("mov.b64 %0,{%1,%2};" : "=l"(r) : "f"(a), "f"(b)); return r;
}
__device__ __forceinline__ void up2(u64 v, float& a, float& b) {
    asm("mov.b64 {%0,%1},%2;" : "=f"(a), "=f"(b) : "l"(v));
}
__device__ __forceinline__ u64 swap2(u64 v) {
    float a, b; up2(v, a, b); return pk2(b, a);
}
__device__ __forceinline__ u64 f2fma(u64 a, u64 b, u64 c) {
    u64 d; asm("fma.rn.f32x2 %0,%1,%2,%3;" : "=l"(d) : "l"(a), "l"(b), "l"(c)); return d;
}
__device__ __forceinline__ u64 f2mul(u64 a, u64 b) {
    u64 d; asm("mul.rn.f32x2 %0,%1,%2;" : "=l"(d) : "l"(a), "l"(b)); return d;
}
__host__ __device__ constexpr u64 PKC(float f) {
    unsigned u = __builtin_bit_cast(unsigned, f);
    return ((u64)u << 32) | (u64)u;
}

// Tsit5 coefficients (fp32)
#define A21 0.161f
#define A31 (-0.008480655492356989f)
#define A32 0.335480655492357f
#define A41 2.8971530571054935f
#define A42 (-6.359448489975075f)
#define A43 4.3622954328695815f
#define A51 5.325864828439257f
#define A52 (-11.748883564062828f)
#define A53 7.4955393428898365f
#define A54 (-0.09249506636175525f)
#define A61 5.86145544294642f
#define A62 (-12.92096931784711f)
#define A63 8.159367898576159f
#define A64 (-0.071584973281401f)
#define A65 (-0.028269050394068383f)
#define B1 0.09646076681806523f
#define B2 0.01f
#define B3 0.4798896504144996f
#define B4 1.379008574103742f
#define B5 (-3.290069515436081f)
#define B6 2.324710524099774f
#define E1 (-0.001780011052225777f)
#define E2 (-0.0008164344596567469f)
#define E3 0.007880878010261995f
#define E4 (-0.1447110071732629f)
#define E5 0.5823571654525552f
#define E6 (-0.45808210592918697f)
#define E7 0.015151515151515152f

// Tolerance tightened 8x vs reference (free-running h makes error test binding).
#define ATOLS 1.25e-9f
#define RTOLS 1.25e-5f
#define PRED_LEN 32

// Max step: bounds the dense-output interpolation span (error ~ h^4).
#define H_MAX 1.6f

// Log-domain controller (R13): accept iff max lane log-ratio <= log2(2),
// bits(fac) = FAC1 - 0.2*lmax.
#define FAC1 1065755873
#define FAC_FIFTH 858993459   // round(0.2 * 2^32)
#define L_TWO (1 << 23)

// Fully-packed RHS: for y=(S,I), SI = y*swap(y) = (S*I, S*I);
// k = gmv*y + bnv*SI = (-bN*SI, bN*SI - gm*I) = (dS, dI).
#define PRHSP(yv, kout)                           \
    {                                             \
        u64 _sw = swap2(yv);                      \
        u64 _si = f2mul((yv), _sw);               \
        kout = f2fma(gmv, (yv), f2mul(bnv, _si)); \
    }

__global__ void __launch_bounds__(32) sird_kernel(
    const float* __restrict__ x,          // [B,3] beta,gamma,mu
    const float* __restrict__ gp,         // [B,1]
    const float* __restrict__ population, // [B]
    float* __restrict__ out,              // [B,32,4]
    int B)
{
    int b = blockIdx.x * blockDim.x + threadIdx.x;
    if (b >= B) return;

    const float beta  = x[3 * b + 0];
    const float gamma = x[3 * b + 1];
    const float mu    = x[3 * b + 2];
    const float N     = population[b];
    const float bN    = beta / N;
    const float gm    = gamma + mu;

    const u64 bnv = pk2(-bN, bN);
    const u64 gmv = pk2(0.0f, -gm);

    float S = gp[b] - 100.0f;
    float I = 100.0f;
    float R = 0.0f;
    float D = 0.0f;

    float4* orow = reinterpret_cast<float4*>(out + (size_t)b * (PRED_LEN * 4));
    orow[0] = make_float4(S, I, R, D);

    const float tstep = 32.0f / 31.0f;
    const float TEND  = 32.0f;

    float dt = 0.05f;
    float t  = 0.0f;
    int ivn = 1;

    // FSAL: k1 = RHS(y) carried across steps (autonomous RHS).
    u64 k1;
    {
        u64 y0 = pk2(S, I);
        PRHSP(y0, k1);
    }

    for (int step = 0; step < 400 && ivn < PRED_LEN; ++step) {
        const float rem = TEND - t;
        const bool capped = dt > rem;
        float h = fmaxf(fminf(fminf(dt, H_MAX), rem), 1e-9f);
        u64 h2 = pk2(h, h);
        u64 y2 = pk2(S, I);

        u64 a2v = f2fma(h2, f2mul(PKC(A21), k1), y2);
        u64 k2; PRHSP(a2v, k2);

        u64 a3v = f2fma(h2, f2fma(PKC(A32), k2, f2mul(PKC(A31), k1)), y2);
        u64 k3; PRHSP(a3v, k3);

        u64 a4v = f2fma(h2, f2fma(PKC(A43), k3, f2fma(PKC(A42), k2, f2mul(PKC(A41), k1))), y2);
        u64 k4; PRHSP(a4v, k4);

        u64 a5v = f2fma(h2, f2fma(PKC(A54), k4, f2fma(PKC(A53), k3, f2fma(PKC(A52), k2, f2mul(PKC(A51), k1)))), y2);
        u64 k5; PRHSP(a5v, k5);

        u64 a6v = f2fma(h2, f2fma(PKC(A65), k5, f2fma(PKC(A64), k4, f2fma(PKC(A63), k3, f2fma(PKC(A62), k2, f2mul(PKC(A61), k1))))), y2);
        u64 k6; PRHSP(a6v, k6);

        u64 ny2 = f2fma(h2,
            f2fma(PKC(B6), k6, f2fma(PKC(B5), k5, f2fma(PKC(B4), k4,
                f2fma(PKC(B3), k3, f2fma(PKC(B2), k2, f2mul(PKC(B1), k1)))))), y2);

        u64 k7; PRHSP(ny2, k7);

        // packed error estimate for (S, I)
        u64 e2 = f2mul(h2,
            f2fma(PKC(E7), k7, f2fma(PKC(E6), k6, f2fma(PKC(E5), k5,
                f2fma(PKC(E4), k4, f2fma(PKC(E3), k3, f2fma(PKC(E2), k2, f2mul(PKC(E1), k1))))))));

        // B-weighted stage-I sum for full-step R/D update (lane1 valid)
        u64 SB2 = f2fma(PKC(B6), a6v, f2fma(PKC(B5), a5v, f2fma(PKC(B4), a4v,
                    f2fma(PKC(B3), a3v, f2fma(PKC(B2), a2v, f2mul(PKC(B1), y2))))));

        float nS, nI, es, ei, dumb, SB;
        up2(ny2, nS, nI);
        up2(e2, es, ei);
        up2(SB2, dumb, SB);

        const float hg = h * gamma;
        const float hm = h * mu;

        float ts_ = fmaf(RTOLS, fmaxf(fabsf(S), fabsf(nS)), ATOLS);
        float ti_ = fmaf(RTOLS, fmaxf(fabsf(I), fabsf(nI)), ATOLS);

        // ---- log-domain controller (divide-free) ----
        int lrs = (int)(__float_as_uint(es) & 0x7fffffffu) - (int)__float_as_uint(ts_);
        int lri = (int)(__float_as_uint(ei) & 0x7fffffffu) - (int)__float_as_uint(ti_);
        int lmax = max(lrs, lri);

        int facb = FAC1 - __mulhi(lmax, FAC_FIFTH);
        float fac = fminf(fmaxf(__int_as_float(facb), 0.2f), 10.0f);
        float dtn = h * fac;

        if (lmax <= L_TWO) {
            // Accepted: flush all output points in (t, t+h] by dense output.
            float tnew = t + h;
            float rcp = __fdividef(1.0f, h);
            while (ivn < PRED_LEN) {
                float tout = (float)ivn * tstep;
                if (tout > tnew + 1e-5f) break;
                float th = fminf((tout - t) * rcp, 1.0f);
                float th2 = th * th;

                // Tsit5 free interpolant b_i(th) (Tsitouras 2011; b_i(1)=B_i verified)
                float b1 = -1.0530884977290216f * th * (th - 1.3299890189751412f)
                           * fmaf(th, th, fmaf(-1.4364028541716351f, th, 0.7139816917074209f));
                float b2 = 0.1017f * th2
                           * fmaf(th, th, fmaf(-2.1966568338249754f, th, 1.2949852507374631f));
                float b3 = 2.490627285651252793f * th2
                           * fmaf(th, th, fmaf(-2.3853564547206166f, th, 1.5780346820809249f));
                float b4 = -16.54810288924490272f * th2
                           * ((th - 1.21712927295533244f) * (th - 0.61620406037800089f));
                float b5 = 47.37952196281928122f * th2
                           * ((th - 1.2030712083723626f) * (th - 0.6580472926535474f));
                float b6 = -34.87065786149660974f * th2
                           * ((th - 1.2f) * (th - 0.6666666666666667f));
                float b7 = 2.5f * th2 * ((th - 1.0f) * (th - 0.6f));

                // y(th) = y + h * sum b_i k_i   (packed S,I)
                u64 acc = f2mul(pk2(b1, b1), k1);
                acc = f2fma(pk2(b2, b2), k2, acc);
                acc = f2fma(pk2(b3, b3), k3, acc);
                acc = f2fma(pk2(b4, b4), k4, acc);
                acc = f2fma(pk2(b5, b5), k5, acc);
                acc = f2fma(pk2(b6, b6), k6, acc);
                acc = f2fma(pk2(b7, b7), k7, acc);
                u64 yo = f2fma(h2, acc, y2);

                // stage-I interpolant for R/D (lane1 valid)
                u64 accI = f2mul(pk2(b1, b1), y2);
                accI = f2fma(pk2(b2, b2), a2v, accI);
                accI = f2fma(pk2(b3, b3), a3v, accI);
                accI = f2fma(pk2(b4, b4), a4v, accI);
                accI = f2fma(pk2(b5, b5), a5v, accI);
                accI = f2fma(pk2(b6, b6), a6v, accI);
                accI = f2fma(pk2(b7, b7), ny2, accI);

                float So, Io, dum0, SIo;
                up2(yo, So, Io);
                up2(accI, dum0, SIo);
                float Ro = fmaf(hg, SIo, R);
                float Do = fmaf(hm, SIo, D);

                orow[ivn] = make_float4(So, Io, Ro, Do);
                ++ivn;
            }

            t = tnew;
            S = nS; I = nI;
            R = fmaf(hg, SB, R);
            D = fmaf(hm, SB, D);
            k1 = k7;  // FSAL
        }

        dt = capped ? fmaxf(dt, dtn) : dtn;
    }

    // Deterministic fallback (should not trigger): flush remaining outputs.
    while (ivn < PRED_LEN) {
        orow[ivn] = make_float4(S, I, R, D);
        ++ivn;
    }
}

extern "C" void kernel_launch(void* const* d_in, const int* in_sizes, int n_in,
                              void* d_out, int out_size)
{
    const float* x   = (const float*)d_in[0];
    const float* gp  = (const float*)d_in[1];
    const float* pop = (const float*)d_in[2];
    float* out = (float*)d_out;
    int B = in_sizes[2];  // population has B elements

    int threads = 32;
    int blocks = (B + threads - 1) / threads;
    sird_kernel<<<blocks, threads>>>(x, gp, pop, out, B);
}